// round 14
// baseline (speedup 1.0000x reference)
#include <cuda_runtime.h>
#include <cstdint>

#define N_NODES 50000
#define IN_FEAT 512
#define OUT_FEAT 256
#define N_EDGES 1600000
#define ALPHA 0.2f

#define A_BLOCKS 64          // blocks participating in phase A (8 warps x 8 rows)

// Scratch (allocation-free rule: __device__ globals).
__device__ float4 g_w_src4[IN_FEAT / 4];
__device__ float4 g_w_tgt4[IN_FEAT / 4];
__device__ float g_s_src[N_NODES];
__device__ float g_s_tgt[N_NODES];

// One-sided release counter for phase A. Reset to 0 by edge_kernel (which is
// strictly ordered after ab_kernel within each replay), so every replay of
// ab_kernel starts from 0. Static init covers the very first run.
__device__ unsigned g_a_done = 0;

__device__ __forceinline__ float dot4(float4 a, float4 b) {
    return a.x * b.x + a.y * b.y + a.z * b.z + a.w * b.w;
}

// ---------------------------------------------------------------------------
// Kernel 1: phase A (w = W @ a, blocks 0..63) -> one-sided release ->
// phase B (node scores). Phase bodies FROZEN from the 36.0us R5 kernel.
// ---------------------------------------------------------------------------
__global__ __launch_bounds__(256) void ab_kernel(
    const float* __restrict__ h,
    const float* __restrict__ W,
    const float* __restrict__ attn_w,
    int nblocks)
{
    __shared__ float4 sh_ws[IN_FEAT / 4];
    __shared__ float4 sh_wt[IN_FEAT / 4];

    const int tid  = threadIdx.x;
    const int lane = tid & 31;
    const int wid  = tid >> 5;
    const int gw   = blockIdx.x * 8 + wid;
    const int nwarps = nblocks * 8;

    // ---------------- Phase A (blocks 0..A_BLOCKS-1 only) ------------------
    if (blockIdx.x < A_BLOCKS) {
        // gw in [0, 512): one warp per W row
        const float4* wrow4 = reinterpret_cast<const float4*>(W + (size_t)gw * OUT_FEAT);
        const float4* as4   = reinterpret_cast<const float4*>(attn_w);
        const float4* at4   = reinterpret_cast<const float4*>(attn_w + OUT_FEAT);

        float4 w0 = wrow4[lane];
        float4 w1 = wrow4[32 + lane];
        float acc_s = dot4(w0, as4[lane]) + dot4(w1, as4[32 + lane]);
        float acc_t = dot4(w0, at4[lane]) + dot4(w1, at4[32 + lane]);
#pragma unroll
        for (int off = 16; off > 0; off >>= 1) {
            acc_s += __shfl_xor_sync(0xffffffffu, acc_s, off);
            acc_t += __shfl_xor_sync(0xffffffffu, acc_t, off);
        }
        if (lane == 0) {
            reinterpret_cast<float*>(g_w_src4)[gw] = acc_s;
            reinterpret_cast<float*>(g_w_tgt4)[gw] = acc_t;
        }
        __syncthreads();                  // block's w-writes complete
        if (tid == 0) {
            __threadfence();              // publish before arrival
            atomicAdd(&g_a_done, 1u);
        }
    }

    // ---------------- One-sided wait: A published? -------------------------
    if (tid == 0) {
        while (*(volatile unsigned*)&g_a_done < A_BLOCKS) { }
        __threadfence();                  // acquire
    }
    __syncthreads();

    // Stage w vectors into shared (4 KB)
    for (int i = tid; i < IN_FEAT / 4; i += 256) {
        sh_ws[i] = g_w_src4[i];
        sh_wt[i] = g_w_tgt4[i];
    }
    __syncthreads();

    // ---------------- Phase B: warp per node, grid-stride (FROZEN) ---------
    for (int node = gw; node < N_NODES; node += nwarps) {
        const float4* h4 = reinterpret_cast<const float4*>(h + (size_t)node * IN_FEAT);

        float4 hv0 = h4[lane];
        float4 hv1 = h4[32 + lane];
        float4 hv2 = h4[64 + lane];
        float4 hv3 = h4[96 + lane];

        float acc_s = dot4(hv0, sh_ws[lane])      + dot4(hv1, sh_ws[32 + lane]) +
                      dot4(hv2, sh_ws[64 + lane]) + dot4(hv3, sh_ws[96 + lane]);
        float acc_t = dot4(hv0, sh_wt[lane])      + dot4(hv1, sh_wt[32 + lane]) +
                      dot4(hv2, sh_wt[64 + lane]) + dot4(hv3, sh_wt[96 + lane]);

        // Split-half reduction: lo 16 lanes reduce s, hi 16 reduce t.
        float os = __shfl_xor_sync(0xffffffffu, acc_s, 16);
        float ot = __shfl_xor_sync(0xffffffffu, acc_t, 16);
        float v = (lane < 16) ? (acc_s + os) : (acc_t + ot);
#pragma unroll
        for (int off = 8; off > 0; off >>= 1)
            v += __shfl_xor_sync(0xffffffffu, v, off);
        if (lane == 0)  g_s_src[node] = v;
        if (lane == 16) g_s_tgt[node] = v;
    }
}

// ---------------------------------------------------------------------------
// Kernel 2: phase C. Single wave (782 blocks ~ 5.3/SM), 2 int4-groups per
// thread (16 outstanding gathers), halves split contiguously so both group
// streams stay warp-coalesced. Also resets g_a_done for the next replay.
// ---------------------------------------------------------------------------
#define C_HALF (N_EDGES / 8)            // 200000 int4-groups per half

__global__ __launch_bounds__(256) void edge_kernel(
    const int* __restrict__ edge_list,
    float*     __restrict__ out)
{
    if (blockIdx.x == 0 && threadIdx.x == 0)
        g_a_done = 0;                    // reset release counter for next replay

    const int k = blockIdx.x * 256 + threadIdx.x;
    if (k >= C_HALF) return;
    const int k2 = k + C_HALF;

    const int4* src4 = reinterpret_cast<const int4*>(edge_list);
    const int4* tgt4 = reinterpret_cast<const int4*>(edge_list + N_EDGES);

    int4 sA = src4[k];
    int4 tA = tgt4[k];
    int4 sB = src4[k2];
    int4 tB = tgt4[k2];

    float a0 = __ldg(&g_s_src[sA.x]) + __ldg(&g_s_tgt[tA.x]);
    float a1 = __ldg(&g_s_src[sA.y]) + __ldg(&g_s_tgt[tA.y]);
    float a2 = __ldg(&g_s_src[sA.z]) + __ldg(&g_s_tgt[tA.z]);
    float a3 = __ldg(&g_s_src[sA.w]) + __ldg(&g_s_tgt[tA.w]);
    float b0 = __ldg(&g_s_src[sB.x]) + __ldg(&g_s_tgt[tB.x]);
    float b1 = __ldg(&g_s_src[sB.y]) + __ldg(&g_s_tgt[tB.y]);
    float b2 = __ldg(&g_s_src[sB.z]) + __ldg(&g_s_tgt[tB.z]);
    float b3 = __ldg(&g_s_src[sB.w]) + __ldg(&g_s_tgt[tB.w]);

    float4 rA, rB;
    rA.x = (a0 > 0.f) ? a0 : ALPHA * a0;
    rA.y = (a1 > 0.f) ? a1 : ALPHA * a1;
    rA.z = (a2 > 0.f) ? a2 : ALPHA * a2;
    rA.w = (a3 > 0.f) ? a3 : ALPHA * a3;
    rB.x = (b0 > 0.f) ? b0 : ALPHA * b0;
    rB.y = (b1 > 0.f) ? b1 : ALPHA * b1;
    rB.z = (b2 > 0.f) ? b2 : ALPHA * b2;
    rB.w = (b3 > 0.f) ? b3 : ALPHA * b3;

    reinterpret_cast<float4*>(out)[k]  = rA;
    reinterpret_cast<float4*>(out)[k2] = rB;
}

// ---------------------------------------------------------------------------
extern "C" void kernel_launch(void* const* d_in, const int* in_sizes, int n_in,
                              void* d_out, int out_size) {
    const float* h         = (const float*)d_in[0];
    const int*   edge_list = (const int*)d_in[1];
    const float* W         = (const float*)d_in[2];
    const float* attn_w    = (const float*)d_in[3];
    float* out = (float*)d_out;

    int dev = 0;
    cudaGetDevice(&dev);
    int sms = 148;
    cudaDeviceGetAttribute(&sms, cudaDevAttrMultiProcessorCount, dev);
    int occ = 1;
    cudaOccupancyMaxActiveBlocksPerMultiprocessor(&occ, ab_kernel, 256, 0);
    if (occ < 1) occ = 1;
    int nblocks_ab = sms * occ;                    // one co-resident wave
    if (nblocks_ab < A_BLOCKS) nblocks_ab = A_BLOCKS;

    ab_kernel<<<nblocks_ab, 256>>>(h, W, attn_w, nblocks_ab);

    // C: 200000 threads covering 2 halves -> 782 blocks of 256
    edge_kernel<<<(C_HALF + 255) / 256, 256>>>(edge_list, out);
}

// round 15
// speedup vs baseline: 1.0313x; 1.0313x over previous
#include <cuda_runtime.h>
#include <cstdint>

#define N_NODES 50000
#define IN_FEAT 512
#define OUT_FEAT 256
#define N_EDGES 1600000
#define ALPHA 0.2f

// Scratch (allocation-free rule: __device__ globals).
__device__ float4 g_w_src4[IN_FEAT / 4];
__device__ float4 g_w_tgt4[IN_FEAT / 4];
__device__ float g_s_src[N_NODES];
__device__ float g_s_tgt[N_NODES];

// Monotonic-ticket grid barrier (no reset; safe across graph replays).
__device__ unsigned g_bar = 0;

__device__ __forceinline__ float dot4(float4 a, float4 b) {
    return a.x * b.x + a.y * b.y + a.z * b.z + a.w * b.w;
}

__device__ __forceinline__ void grid_sync(unsigned nblocks) {
    __syncthreads();
    if (threadIdx.x == 0) {
        __threadfence();
        unsigned ticket = atomicAdd(&g_bar, 1u);
        unsigned target = (ticket / nblocks + 1u) * nblocks;
        while (*(volatile unsigned*)&g_bar < target) { }
        __threadfence();
    }
    __syncthreads();
}

// ---------------------------------------------------------------------------
// Kernel 1: phase A (w = W @ a) -> grid barrier -> phase B (node scores).
// FROZEN: byte-identical to the R13 35.3us version.
// ---------------------------------------------------------------------------
__global__ __launch_bounds__(256) void ab_kernel(
    const float* __restrict__ h,
    const float* __restrict__ W,
    const float* __restrict__ attn_w,
    int nblocks)
{
    __shared__ float4 sh_ws[IN_FEAT / 4];
    __shared__ float4 sh_wt[IN_FEAT / 4];

    const int tid  = threadIdx.x;
    const int lane = tid & 31;
    const int wid  = tid >> 5;
    const int gw   = blockIdx.x * 8 + wid;
    const int nwarps = nblocks * 8;

    // ---------------- Phase A ----------------------------------------------
    if (gw < IN_FEAT) {
        const float4* wrow4 = reinterpret_cast<const float4*>(W + (size_t)gw * OUT_FEAT);
        const float4* as4   = reinterpret_cast<const float4*>(attn_w);
        const float4* at4   = reinterpret_cast<const float4*>(attn_w + OUT_FEAT);

        float4 w0 = wrow4[lane];
        float4 w1 = wrow4[32 + lane];
        float acc_s = dot4(w0, as4[lane]) + dot4(w1, as4[32 + lane]);
        float acc_t = dot4(w0, at4[lane]) + dot4(w1, at4[32 + lane]);
#pragma unroll
        for (int off = 16; off > 0; off >>= 1) {
            acc_s += __shfl_xor_sync(0xffffffffu, acc_s, off);
            acc_t += __shfl_xor_sync(0xffffffffu, acc_t, off);
        }
        if (lane == 0) {
            reinterpret_cast<float*>(g_w_src4)[gw] = acc_s;
            reinterpret_cast<float*>(g_w_tgt4)[gw] = acc_t;
        }
    }

    grid_sync(nblocks);

    // Stage w vectors into shared (4 KB)
    for (int i = tid; i < IN_FEAT / 4; i += 256) {
        sh_ws[i] = g_w_src4[i];
        sh_wt[i] = g_w_tgt4[i];
    }
    __syncthreads();

    // ---------------- Phase B: warp per node, grid-stride ------------------
    for (int node = gw; node < N_NODES; node += nwarps) {
        const float4* h4 = reinterpret_cast<const float4*>(h + (size_t)node * IN_FEAT);

        float4 hv0 = h4[lane];
        float4 hv1 = h4[32 + lane];
        float4 hv2 = h4[64 + lane];
        float4 hv3 = h4[96 + lane];

        float acc_s = dot4(hv0, sh_ws[lane])      + dot4(hv1, sh_ws[32 + lane]) +
                      dot4(hv2, sh_ws[64 + lane]) + dot4(hv3, sh_ws[96 + lane]);
        float acc_t = dot4(hv0, sh_wt[lane])      + dot4(hv1, sh_wt[32 + lane]) +
                      dot4(hv2, sh_wt[64 + lane]) + dot4(hv3, sh_wt[96 + lane]);

        // Split-half reduction: lo 16 lanes reduce s, hi 16 reduce t.
        float os = __shfl_xor_sync(0xffffffffu, acc_s, 16);
        float ot = __shfl_xor_sync(0xffffffffu, acc_t, 16);
        float v = (lane < 16) ? (acc_s + os) : (acc_t + ot);
#pragma unroll
        for (int off = 8; off > 0; off >>= 1)
            v += __shfl_xor_sync(0xffffffffu, v, off);
        if (lane == 0)  g_s_src[node] = v;
        if (lane == 16) g_s_tgt[node] = v;
    }
}

// ---------------------------------------------------------------------------
// Kernel 2: phase C. Balanced grid-stride over exactly one resident wave
// (8 blocks/SM x 148 SMs = 1184 blocks): every SM gets the same share of the
// 400000 int4-groups, no ragged 1.3-wave tail. Body identical to the R13
// 14.2us version (1 int4-group / 8 gathers per iteration).
// ---------------------------------------------------------------------------
#define C_BLOCKS 1184
#define C_THREADS 256

__global__ __launch_bounds__(C_THREADS) void edge_kernel(
    const int* __restrict__ edge_list,
    float*     __restrict__ out)
{
    const int n4 = N_EDGES / 4;
    const int stride = C_BLOCKS * C_THREADS;
    const int4*  src4 = reinterpret_cast<const int4*>(edge_list);
    const int4*  tgt4 = reinterpret_cast<const int4*>(edge_list + N_EDGES);
    float4*      out4 = reinterpret_cast<float4*>(out);

    for (int k4 = blockIdx.x * C_THREADS + threadIdx.x; k4 < n4; k4 += stride) {
        int4 s = src4[k4];
        int4 t = tgt4[k4];

        float e0 = __ldg(&g_s_src[s.x]) + __ldg(&g_s_tgt[t.x]);
        float e1 = __ldg(&g_s_src[s.y]) + __ldg(&g_s_tgt[t.y]);
        float e2 = __ldg(&g_s_src[s.z]) + __ldg(&g_s_tgt[t.z]);
        float e3 = __ldg(&g_s_src[s.w]) + __ldg(&g_s_tgt[t.w]);

        float4 r;
        r.x = fmaxf(e0, ALPHA * e0);   // leaky_relu: max(e, 0.2e) for both signs
        r.y = fmaxf(e1, ALPHA * e1);
        r.z = fmaxf(e2, ALPHA * e2);
        r.w = fmaxf(e3, ALPHA * e3);
        out4[k4] = r;
    }
}

// ---------------------------------------------------------------------------
extern "C" void kernel_launch(void* const* d_in, const int* in_sizes, int n_in,
                              void* d_out, int out_size) {
    const float* h         = (const float*)d_in[0];
    const int*   edge_list = (const int*)d_in[1];
    const float* W         = (const float*)d_in[2];
    const float* attn_w    = (const float*)d_in[3];
    float* out = (float*)d_out;

    int dev = 0;
    cudaGetDevice(&dev);
    int sms = 148;
    cudaDeviceGetAttribute(&sms, cudaDevAttrMultiProcessorCount, dev);
    int occ = 1;
    cudaOccupancyMaxActiveBlocksPerMultiprocessor(&occ, ab_kernel, 256, 0);
    if (occ < 1) occ = 1;
    int nblocks_ab = sms * occ;            // exactly one co-resident wave
    if (nblocks_ab < 64) nblocks_ab = 64;  // phase A needs >= 512 warps

    ab_kernel<<<nblocks_ab, 256>>>(h, W, attn_w, nblocks_ab);

    // C: one exact resident wave, balanced grid-stride
    edge_kernel<<<C_BLOCKS, C_THREADS>>>(edge_list, out);
}

// round 16
// speedup vs baseline: 1.0437x; 1.0120x over previous
#include <cuda_runtime.h>
#include <cstdint>

#define N_NODES 50000
#define IN_FEAT 512
#define OUT_FEAT 256
#define N_EDGES 1600000
#define ALPHA 0.2f

// Scratch (allocation-free rule: __device__ globals).
__device__ float4 g_w_src4[IN_FEAT / 4];
__device__ float4 g_w_tgt4[IN_FEAT / 4];
__device__ float g_s_src[N_NODES];
__device__ float g_s_tgt[N_NODES];

// Monotonic-ticket grid barrier (no reset; safe across graph replays).
__device__ unsigned g_bar = 0;

__device__ __forceinline__ float dot4(float4 a, float4 b) {
    return a.x * b.x + a.y * b.y + a.z * b.z + a.w * b.w;
}

__device__ __forceinline__ void grid_sync(unsigned nblocks) {
    __syncthreads();
    if (threadIdx.x == 0) {
        __threadfence();
        unsigned ticket = atomicAdd(&g_bar, 1u);
        unsigned target = (ticket / nblocks + 1u) * nblocks;
        while (*(volatile unsigned*)&g_bar < target) { }
        __threadfence();
    }
    __syncthreads();
}

// ---------------------------------------------------------------------------
// Kernel 1: phase A (w = W @ a) -> grid barrier -> phase B (node scores).
// FROZEN: byte-identical to the R13 35.3us version.
// ---------------------------------------------------------------------------
__global__ __launch_bounds__(256) void ab_kernel(
    const float* __restrict__ h,
    const float* __restrict__ W,
    const float* __restrict__ attn_w,
    int nblocks)
{
    __shared__ float4 sh_ws[IN_FEAT / 4];
    __shared__ float4 sh_wt[IN_FEAT / 4];

    const int tid  = threadIdx.x;
    const int lane = tid & 31;
    const int wid  = tid >> 5;
    const int gw   = blockIdx.x * 8 + wid;
    const int nwarps = nblocks * 8;

    // ---------------- Phase A ----------------------------------------------
    if (gw < IN_FEAT) {
        const float4* wrow4 = reinterpret_cast<const float4*>(W + (size_t)gw * OUT_FEAT);
        const float4* as4   = reinterpret_cast<const float4*>(attn_w);
        const float4* at4   = reinterpret_cast<const float4*>(attn_w + OUT_FEAT);

        float4 w0 = wrow4[lane];
        float4 w1 = wrow4[32 + lane];
        float acc_s = dot4(w0, as4[lane]) + dot4(w1, as4[32 + lane]);
        float acc_t = dot4(w0, at4[lane]) + dot4(w1, at4[32 + lane]);
#pragma unroll
        for (int off = 16; off > 0; off >>= 1) {
            acc_s += __shfl_xor_sync(0xffffffffu, acc_s, off);
            acc_t += __shfl_xor_sync(0xffffffffu, acc_t, off);
        }
        if (lane == 0) {
            reinterpret_cast<float*>(g_w_src4)[gw] = acc_s;
            reinterpret_cast<float*>(g_w_tgt4)[gw] = acc_t;
        }
    }

    grid_sync(nblocks);

    // Stage w vectors into shared (4 KB)
    for (int i = tid; i < IN_FEAT / 4; i += 256) {
        sh_ws[i] = g_w_src4[i];
        sh_wt[i] = g_w_tgt4[i];
    }
    __syncthreads();

    // ---------------- Phase B: warp per node, grid-stride ------------------
    for (int node = gw; node < N_NODES; node += nwarps) {
        const float4* h4 = reinterpret_cast<const float4*>(h + (size_t)node * IN_FEAT);

        float4 hv0 = h4[lane];
        float4 hv1 = h4[32 + lane];
        float4 hv2 = h4[64 + lane];
        float4 hv3 = h4[96 + lane];

        float acc_s = dot4(hv0, sh_ws[lane])      + dot4(hv1, sh_ws[32 + lane]) +
                      dot4(hv2, sh_ws[64 + lane]) + dot4(hv3, sh_ws[96 + lane]);
        float acc_t = dot4(hv0, sh_wt[lane])      + dot4(hv1, sh_wt[32 + lane]) +
                      dot4(hv2, sh_wt[64 + lane]) + dot4(hv3, sh_wt[96 + lane]);

        // Split-half reduction: lo 16 lanes reduce s, hi 16 reduce t.
        float os = __shfl_xor_sync(0xffffffffu, acc_s, 16);
        float ot = __shfl_xor_sync(0xffffffffu, acc_t, 16);
        float v = (lane < 16) ? (acc_s + os) : (acc_t + ot);
#pragma unroll
        for (int off = 8; off > 0; off >>= 1)
            v += __shfl_xor_sync(0xffffffffu, v, off);
        if (lane == 0)  g_s_src[node] = v;
        if (lane == 16) g_s_tgt[node] = v;
    }
}

// ---------------------------------------------------------------------------
// Kernel 2: phase C with PDL prologue. Exact-fit grid (R13's proven 14.2us
// configuration: 1563 blocks, 1 int4-group/thread). Index loads (independent
// of ab_kernel's output) issue BEFORE cudaGridDependencySynchronize(), so
// with programmatic launch they overlap ab_kernel's tail; score gathers wait
// behind the dependency sync.
// ---------------------------------------------------------------------------
__global__ __launch_bounds__(256) void edge_kernel(
    const int* __restrict__ edge_list,
    float*     __restrict__ out)
{
    const int k4 = blockIdx.x * 256 + threadIdx.x;
    const bool valid = (k4 < N_EDGES / 4);

    int4 s = make_int4(0, 0, 0, 0);
    int4 t = make_int4(0, 0, 0, 0);
    if (valid) {
        s = reinterpret_cast<const int4*>(edge_list)[k4];
        t = reinterpret_cast<const int4*>(edge_list + N_EDGES)[k4];
    }

    // Wait for ab_kernel's grid to fully complete before reading scores.
    cudaGridDependencySynchronize();

    if (!valid) return;

    float e0 = __ldg(&g_s_src[s.x]) + __ldg(&g_s_tgt[t.x]);
    float e1 = __ldg(&g_s_src[s.y]) + __ldg(&g_s_tgt[t.y]);
    float e2 = __ldg(&g_s_src[s.z]) + __ldg(&g_s_tgt[t.z]);
    float e3 = __ldg(&g_s_src[s.w]) + __ldg(&g_s_tgt[t.w]);

    float4 r;
    r.x = fmaxf(e0, ALPHA * e0);   // leaky_relu (valid for both signs)
    r.y = fmaxf(e1, ALPHA * e1);
    r.z = fmaxf(e2, ALPHA * e2);
    r.w = fmaxf(e3, ALPHA * e3);
    reinterpret_cast<float4*>(out)[k4] = r;
}

// ---------------------------------------------------------------------------
extern "C" void kernel_launch(void* const* d_in, const int* in_sizes, int n_in,
                              void* d_out, int out_size) {
    const float* h         = (const float*)d_in[0];
    const int*   edge_list = (const int*)d_in[1];
    const float* W         = (const float*)d_in[2];
    const float* attn_w    = (const float*)d_in[3];
    float* out = (float*)d_out;

    int dev = 0;
    cudaGetDevice(&dev);
    int sms = 148;
    cudaDeviceGetAttribute(&sms, cudaDevAttrMultiProcessorCount, dev);
    int occ = 1;
    cudaOccupancyMaxActiveBlocksPerMultiprocessor(&occ, ab_kernel, 256, 0);
    if (occ < 1) occ = 1;
    int nblocks_ab = sms * occ;            // exactly one co-resident wave
    if (nblocks_ab < 64) nblocks_ab = 64;  // phase A needs >= 512 warps

    ab_kernel<<<nblocks_ab, 256>>>(h, W, attn_w, nblocks_ab);

    // C with programmatic dependent launch: prologue overlaps ab_kernel tail.
    cudaLaunchConfig_t cfg = {};
    cfg.gridDim  = dim3((N_EDGES / 4 + 255) / 256, 1, 1);   // 1563 blocks
    cfg.blockDim = dim3(256, 1, 1);
    cfg.dynamicSmemBytes = 0;
    cfg.stream = 0;                         // legacy default stream (captured)
    cudaLaunchAttribute attrs[1];
    attrs[0].id = cudaLaunchAttributeProgrammaticStreamSerialization;
    attrs[0].val.programmaticStreamSerializationAllowed = 1;
    cfg.attrs = attrs;
    cfg.numAttrs = 1;
    cudaError_t err = cudaLaunchKernelEx(&cfg, edge_kernel, edge_list, out);
    if (err != cudaSuccess) {
        // Fallback: plain serialized launch (identical semantics).
        edge_kernel<<<(N_EDGES / 4 + 255) / 256, 256>>>(edge_list, out);
    }
}